// round 10
// baseline (speedup 1.0000x reference)
#include <cuda_runtime.h>
#include <math_constants.h>

// Problem constants (fixed by the reference):
//   outputs: (B, C) fp32, targets: (B,) i32, ages: (B,) i32, weight: (C,) fp32
//   T = 2.0 softmax temperature; output = scalar fp32 mean loss.
//
// R10 design: best-measured stage-1 (float4 two-pass, 256thr/8rows) with a
// near-zero-cost fused tail: per-block partial quantized to s63.40 fixed
// point and REDG-added (no return, no fence) to one u64 accumulator.
// Integer adds are order-independent -> bit-deterministic. Only ONE thread
// per block runs the tail (no extra __syncthreads holding warps alive);
// only the single last block pays one acquire fence.
#define B_ROWS 32768
#define C_COLS 1024
#define ROWS_PER_BLOCK 8
#define THREADS (ROWS_PER_BLOCK * 32)
#define NBLOCKS (B_ROWS / ROWS_PER_BLOCK) // 4096
#define FP_SCALE 1099511627776.0f         // 2^40

__device__ unsigned long long g_sum = 0ULL;
__device__ unsigned int g_count = 0;

__global__ __launch_bounds__(THREADS)
void loss_fused_kernel(const float* __restrict__ outputs,
                       const int*   __restrict__ targets,
                       const int*   __restrict__ ages,
                       const float* __restrict__ weight,
                       float*       __restrict__ out) {
    const int warp = threadIdx.x >> 5;
    const int lane = threadIdx.x & 31;
    const int row  = blockIdx.x * ROWS_PER_BLOCK + warp;

    const float4* rp = reinterpret_cast<const float4*>(
        outputs + (size_t)row * C_COLS);

    // Register-resident row; two-pass max->exp keeps all values live so
    // ptxas front-batches all 8 LDG.128 (fastest measured shape, R1-R9).
    float4 v[8];
#pragma unroll
    for (int k = 0; k < 8; ++k) v[k] = __ldcs(&rp[k * 32 + lane]);

    // Pass 1: scale by 1/T and per-lane max (4 parallel max chains).
    float m0 = -CUDART_INF_F, m1 = -CUDART_INF_F;
    float m2 = -CUDART_INF_F, m3 = -CUDART_INF_F;
#pragma unroll
    for (int k = 0; k < 8; ++k) {
        v[k].x *= 0.5f; v[k].y *= 0.5f; v[k].z *= 0.5f; v[k].w *= 0.5f;
        m0 = fmaxf(m0, v[k].x); m1 = fmaxf(m1, v[k].y);
        m2 = fmaxf(m2, v[k].z); m3 = fmaxf(m3, v[k].w);
    }
    float m = fmaxf(fmaxf(m0, m1), fmaxf(m2, m3));
#pragma unroll
    for (int off = 16; off > 0; off >>= 1)
        m = fmaxf(m, __shfl_xor_sync(0xFFFFFFFFu, m, off));

    // Pass 2: exp-sum with 4 parallel accumulators.
    float s0 = 0.0f, s1 = 0.0f, s2 = 0.0f, s3 = 0.0f;
#pragma unroll
    for (int k = 0; k < 8; ++k) {
        s0 += __expf(v[k].x - m);
        s1 += __expf(v[k].y - m);
        s2 += __expf(v[k].z - m);
        s3 += __expf(v[k].w - m);
    }
    float s = (s0 + s1) + (s2 + s3);
#pragma unroll
    for (int off = 16; off > 0; off >>= 1)
        s += __shfl_xor_sync(0xFFFFFFFFu, s, off);

    __shared__ float sh[ROWS_PER_BLOCK];
    if (lane == 0) {
        const float lse = m + __logf(s);
        const int   t    = targets[row];
        const float agef = (float)ages[row];
        const float delta = (agef > 50.0f && agef < 60.0f)
                                ? (agef - 50.0f) * 0.1f : 0.0f;
        // Re-reads of this row hit L1 (lines just streamed by this warp).
        const float yt  = outputs[(size_t)row * C_COLS + t]     * 0.5f;
        const float yt1 = outputs[(size_t)row * C_COLS + t + 1] * 0.5f;
        const float loss = -((1.0f - delta) * weight[t]     * (yt  - lse)
                           +         delta  * weight[t + 1] * (yt1 - lse));
        sh[warp] = loss;
    }
    __syncthreads();

    // Tail: thread 0 only; all other warps retire immediately.
    if (threadIdx.x != 0) return;

    float p = 0.0f;
#pragma unroll
    for (int i = 0; i < ROWS_PER_BLOCK; ++i) p += sh[i];

    // Deterministic fixed-point accumulate: REDG (no return, no fence).
    const long long q = llrintf(p * FP_SCALE);
    atomicAdd(&g_sum, (unsigned long long)q); // result unused -> REDG

    // Release orders the REDG above before the counter increment.
    unsigned int prev;
    asm volatile("atom.add.release.gpu.u32 %0, [%1], 1;"
                 : "=r"(prev) : "l"(&g_count) : "memory");
    if (prev != (unsigned int)(NBLOCKS - 1)) return;

    // Last block only: one acquire fence for the whole kernel, then read.
    asm volatile("fence.acq_rel.gpu;" ::: "memory");
    const unsigned long long total = atomicAdd(&g_sum, 0ULL);
    const double mean = (double)(long long)total
                        * (1.0 / ((double)FP_SCALE * (double)B_ROWS));
    out[0] = (float)mean;

    // Reset for next graph replay (ordered by the kernel boundary).
    g_sum   = 0ULL;
    g_count = 0;
}

extern "C" void kernel_launch(void* const* d_in, const int* in_sizes, int n_in,
                              void* d_out, int out_size) {
    const float* outputs = (const float*)d_in[0];
    const int*   targets = (const int*)d_in[1];
    const int*   ages    = (const int*)d_in[2];
    const float* weight  = (const float*)d_in[3];
    float*       out     = (float*)d_out;

    loss_fused_kernel<<<NBLOCKS, THREADS>>>(outputs, targets, ages, weight, out);
}